// round 7
// baseline (speedup 1.0000x reference)
#include <cuda_runtime.h>
#include <cuda_bf16.h>
#include <math.h>

// ---------------- problem constants ----------------
#define TT      8192
#define DIN     1728
#define HID     512
#define GATES   2048
#define Y1DIM   1024
#define TAGS    27
#define STARTT  25
#define STOPT   26

// recurrence partitioning: 64 CTAs per direction, 8 hidden units per CTA (1 per warp)
#define RC_C    64
#define RC_U    8

// ---------------- device scratch ----------------
__device__ float d_x   [TT * DIN];
__device__ float d_gxf [TT * GATES];
__device__ float d_gxr [TT * GATES];
__device__ float d_y0  [TT * Y1DIM];
__device__ float d_y1  [TT * Y1DIM];
__device__ float d_logits[TT * 32];

// self-validating mailboxes: [layer][dir][slot][unit]
// each float carries (step & 3) in its 2 LSBs; slot = step & 1
__device__ float d_mail[2][2][2][RC_C * RC_U];

// ---------------- f32x2 helpers ----------------
__device__ __forceinline__ void ffma2(unsigned long long& d,
                                      unsigned long long a, unsigned long long b) {
    asm("fma.rn.f32x2 %0, %1, %2, %0;" : "+l"(d) : "l"(a), "l"(b));
}
__device__ __forceinline__ unsigned long long pack2(float x, float y) {
    unsigned long long r;
    asm("mov.b64 %0, {%1, %2};" : "=l"(r) : "f"(x), "f"(y));
    return r;
}
__device__ __forceinline__ float2 unpack2(unsigned long long v) {
    float2 r;
    asm("mov.b64 {%0, %1}, %2;" : "=f"(r.x), "=f"(r.y) : "l"(v));
    return r;
}

// fast gates (MUFU-based, clamp-safe)
__device__ __forceinline__ float sigm_f(float x) {
    return __fdividef(1.f, 1.f + __expf(-x));
}
__device__ __forceinline__ float tanh_f(float x) {
    float e = __expf(-2.f * fabsf(x));          // e in (0,1] -> no inf/NaN
    float r = __fdividef(1.f - e, 1.f + e);
    return copysignf(r, x);
}

// ---------------- mailbox poison ----------------
// slot0 holds even-step tags {0,2}: poison with tag 1.
// slot1 holds odd-step tags {1,3}: poison with tag 0.
__global__ void zero_mail_kernel()
{
    float* base = &d_mail[0][0][0][0];
    const int total = 2 * 2 * 2 * RC_C * RC_U;          // 4096
    for (int i = threadIdx.x; i < total; i += blockDim.x) {
        int slot = (i >> 9) & 1;
        unsigned bits = slot ? 0u : 1u;
        base[i] = __uint_as_float(bits);
    }
}

// ---------------- conv feature kernel ----------------
__global__ void conv_kernel(const float* __restrict__ F,
                            const float* __restrict__ W1, const float* __restrict__ B1,
                            const float* __restrict__ W3, const float* __restrict__ B3,
                            const float* __restrict__ W5, const float* __restrict__ B5,
                            float* __restrict__ X)
{
    int t = blockIdx.x;
    __shared__ float fsh[448];
    __shared__ float w1s[448];
    __shared__ float w3s[768];
    __shared__ float w5s[1280];
    __shared__ float b1s[16], b3s[16], b5s[16];
    int tid = threadIdx.x;   // 128 threads

    for (int i = tid; i < 448;  i += 128) fsh[i] = F[t * 448 + i];
    for (int i = tid; i < 448;  i += 128) w1s[i] = W1[i];
    for (int i = tid; i < 768;  i += 128) w3s[i] = W3[i];
    for (int i = tid; i < 1280; i += 128) w5s[i] = W5[i];
    if (tid < 16) { b1s[tid] = B1[tid]; b3s[tid] = B3[tid]; b5s[tid] = B5[tid]; }
    __syncthreads();

    for (int idx = tid; idx < DIN; idx += 128) {
        float acc;
        if (idx < 192) {
            int c = idx / 12, w = idx % 12;
            acc = b1s[c];
            #pragma unroll
            for (int kh = 0; kh < 7; kh++)
                #pragma unroll
                for (int kw = 0; kw < 4; kw++)
                    acc = fmaf(fsh[kh * 64 + w * 4 + kw], w1s[c * 28 + kh * 4 + kw], acc);
        } else if (idx < 960) {
            int j = idx - 192;
            int c = j / 48, r = j % 48, h = r / 12, w = r % 12;
            acc = b3s[c];
            #pragma unroll
            for (int kh = 0; kh < 4; kh++)
                #pragma unroll
                for (int kw = 0; kw < 12; kw++)
                    acc = fmaf(fsh[(h + kh) * 64 + w * 4 + kw], w3s[c * 48 + kh * 12 + kw], acc);
        } else {
            int j = idx - 960;
            int c = j / 48, r = j % 48, h = r / 12, w = r % 12;
            acc = b5s[c];
            #pragma unroll
            for (int kh = 0; kh < 4; kh++)
                #pragma unroll
                for (int kw = 0; kw < 20; kw++)
                    acc = fmaf(fsh[(h + kh) * 64 + w * 4 + kw], w5s[c * 80 + kh * 20 + kw], acc);
        }
        X[(size_t)t * DIN + idx] = acc;
    }
}

// ---------------- fp32 tiled GEMM (double-buffered, f32x2 compute), dual weight sets ----
__global__ __launch_bounds__(256) void gemm_dual_kernel(
    const float* __restrict__ A,
    const float* __restrict__ B0, const float* __restrict__ b0a,
    const float* __restrict__ b0b, float* __restrict__ C0,
    const float* __restrict__ B1, const float* __restrict__ b1a,
    const float* __restrict__ b1b, float* __restrict__ C1,
    int M, int N, int K)
{
    const float* B     = blockIdx.z ? B1  : B0;
    const float* bias1 = blockIdx.z ? b1a : b0a;
    const float* bias2 = blockIdx.z ? b1b : b0b;
    float*       C     = blockIdx.z ? C1  : C0;

    __shared__ __align__(16) float As[2][16][128];
    __shared__ __align__(16) float Bs[2][16][128];
    const int tid = threadIdx.x;
    const int m0 = blockIdx.y * 128;
    const int n0 = blockIdx.x * 128;
    const int tx = tid & 15;
    const int ty = tid >> 4;

    const int row0 = tid >> 2;
    const int row1 = row0 + 64;
    const int kq4  = (tid & 3) * 4;

    const float* Ap0 = A + (size_t)(m0 + row0) * K + kq4;
    const float* Ap1 = A + (size_t)(m0 + row1) * K + kq4;
    const float* Bp0 = B + (size_t)(n0 + row0) * K + kq4;
    const float* Bp1 = B + (size_t)(n0 + row1) * K + kq4;

    unsigned long long acc2[8][4];
    #pragma unroll
    for (int i = 0; i < 8; i++)
        #pragma unroll
        for (int j = 0; j < 4; j++) acc2[i][j] = 0ull;

    float4 pa0 = *(const float4*)(Ap0);
    float4 pa1 = *(const float4*)(Ap1);
    float4 pb0 = *(const float4*)(Bp0);
    float4 pb1 = *(const float4*)(Bp1);

    As[0][kq4 + 0][row0] = pa0.x; As[0][kq4 + 1][row0] = pa0.y;
    As[0][kq4 + 2][row0] = pa0.z; As[0][kq4 + 3][row0] = pa0.w;
    As[0][kq4 + 0][row1] = pa1.x; As[0][kq4 + 1][row1] = pa1.y;
    As[0][kq4 + 2][row1] = pa1.z; As[0][kq4 + 3][row1] = pa1.w;
    Bs[0][kq4 + 0][row0] = pb0.x; Bs[0][kq4 + 1][row0] = pb0.y;
    Bs[0][kq4 + 2][row0] = pb0.z; Bs[0][kq4 + 3][row0] = pb0.w;
    Bs[0][kq4 + 0][row1] = pb1.x; Bs[0][kq4 + 1][row1] = pb1.y;
    Bs[0][kq4 + 2][row1] = pb1.z; Bs[0][kq4 + 3][row1] = pb1.w;
    __syncthreads();

    int buf = 0;
    for (int k0 = 0; k0 < K; k0 += 16) {
        const bool more = (k0 + 16) < K;
        if (more) {
            pa0 = *(const float4*)(Ap0 + k0 + 16);
            pa1 = *(const float4*)(Ap1 + k0 + 16);
            pb0 = *(const float4*)(Bp0 + k0 + 16);
            pb1 = *(const float4*)(Bp1 + k0 + 16);
        }

        #pragma unroll
        for (int k = 0; k < 16; k++) {
            float4 a0 = *(const float4*)&As[buf][k][ty * 8];
            float4 a1 = *(const float4*)&As[buf][k][ty * 8 + 4];
            unsigned long long b2[4];
            {
                const ulonglong2* bp = (const ulonglong2*)&Bs[buf][k][tx * 8];
                ulonglong2 v0 = bp[0], v1 = bp[1];
                b2[0] = v0.x; b2[1] = v0.y; b2[2] = v1.x; b2[3] = v1.y;
            }
            float av[8] = {a0.x, a0.y, a0.z, a0.w, a1.x, a1.y, a1.z, a1.w};
            #pragma unroll
            for (int i = 0; i < 8; i++) {
                unsigned long long ai = pack2(av[i], av[i]);
                #pragma unroll
                for (int jp = 0; jp < 4; jp++)
                    ffma2(acc2[i][jp], ai, b2[jp]);
            }
        }

        if (more) {
            int nb = buf ^ 1;
            As[nb][kq4 + 0][row0] = pa0.x; As[nb][kq4 + 1][row0] = pa0.y;
            As[nb][kq4 + 2][row0] = pa0.z; As[nb][kq4 + 3][row0] = pa0.w;
            As[nb][kq4 + 0][row1] = pa1.x; As[nb][kq4 + 1][row1] = pa1.y;
            As[nb][kq4 + 2][row1] = pa1.z; As[nb][kq4 + 3][row1] = pa1.w;
            Bs[nb][kq4 + 0][row0] = pb0.x; Bs[nb][kq4 + 1][row0] = pb0.y;
            Bs[nb][kq4 + 2][row0] = pb0.z; Bs[nb][kq4 + 3][row0] = pb0.w;
            Bs[nb][kq4 + 0][row1] = pb1.x; Bs[nb][kq4 + 1][row1] = pb1.y;
            Bs[nb][kq4 + 2][row1] = pb1.z; Bs[nb][kq4 + 3][row1] = pb1.w;
            __syncthreads();
            buf = nb;
        }
    }

    #pragma unroll
    for (int i = 0; i < 8; i++) {
        int m = m0 + ty * 8 + i;
        float* Crow = C + (size_t)m * N + n0 + tx * 8;
        #pragma unroll
        for (int jp = 0; jp < 4; jp++) {
            float2 v = unpack2(acc2[i][jp]);
            int n = n0 + tx * 8 + 2 * jp;
            Crow[2 * jp + 0] = v.x + bias1[n + 0] + bias2[n + 0];
            Crow[2 * jp + 1] = v.y + bias1[n + 1] + bias2[n + 1];
        }
    }
}

// ---------------- persistent bidirectional LSTM recurrence ----------------
// grid = 128 CTAs: [0,64) forward, [64,128) backward; 256 threads each.
// Warp w owns hidden unit u0+w: 4 gate rows x 8 k-threads (64 k each).
// Reduction is intra-warp shfl; each warp publishes its own h -> one barrier/step.
// h exchange: self-tagged double-buffered L2 mailboxes, single hop.
__global__ __launch_bounds__(256, 1) void recur_kernel(
    const float* __restrict__ gx_f, const float* __restrict__ gx_r,
    const float* __restrict__ whh_f, const float* __restrict__ whh_r,
    float* __restrict__ y, int layer)
{
    const int dir = blockIdx.x >> 6;
    const int cta = blockIdx.x & 63;
    const float* __restrict__ gx  = dir ? gx_r  : gx_f;
    const float* __restrict__ whh = dir ? whh_r : whh_f;
    float* slotA = &d_mail[layer][dir][0][0];
    float* slotB = &d_mail[layer][dir][1][0];

    const int u0   = cta * RC_U;
    const int tid  = threadIdx.x;
    const int warp = tid >> 5, lane = tid & 31;

    const int gate = lane >> 3;               // 0=i 1=f 2=g 3=o
    const int ksub = lane & 7;                // k-slice owner (8 x 64)
    const int unit = u0 + warp;
    const int grow = gate * 512 + unit;       // global gate row in Whh / gx

    __shared__ __align__(16) float hsh[2][512];   // double-buffered h

    // weights: 64 floats/thread, interleaved 16B chunks {ksub + 8j} for
    // conflict-free LDS (chunk c covers k in [4c, 4c+4))
    unsigned long long w2[32];
    {
        const ulonglong2* wp = (const ulonglong2*)(whh + (size_t)grow * 512);
        #pragma unroll
        for (int j = 0; j < 16; j++) {
            ulonglong2 v = wp[ksub + 8 * j];
            w2[2 * j] = v.x; w2[2 * j + 1] = v.y;
        }
    }

    float c_state = 0.f;   // meaningful in lane 0 of each warp

    for (int s = 0; s < TT; s++) {
        const int tt = dir ? (TT - 1 - s) : s;
        const int buf = s & 1;

        // prefetch gx for this thread's gate row (only ksub==0 lanes use it)
        float gxv = 0.f;
        if (ksub == 0) gxv = gx[(size_t)tt * GATES + grow];

        if (s > 0) {
            // poll peer granules: tid<128, one 16B granule (4 self-tagged floats)
            if (tid < 128) {
                const float* src = (((s - 1) & 1) ? slotB : slotA) + (tid << 2);
                const unsigned want = (unsigned)((s - 1) & 3);
                float4 v;
                unsigned bad;
                do {
                    asm volatile("ld.volatile.global.v4.f32 {%0,%1,%2,%3}, [%4];"
                                 : "=f"(v.x), "=f"(v.y), "=f"(v.z), "=f"(v.w)
                                 : "l"(src));
                    bad  = (__float_as_uint(v.x) & 3u) ^ want;
                    bad |= (__float_as_uint(v.y) & 3u) ^ want;
                    bad |= (__float_as_uint(v.z) & 3u) ^ want;
                    bad |= (__float_as_uint(v.w) & 3u) ^ want;
                } while (bad);
                *(float4*)&hsh[buf][tid << 2] = v;
            }
        }
        __syncthreads();   // single barrier per step (hsh double-buffered)

        // matvec partial over this thread's interleaved 64-k slice
        float part = 0.f;
        if (s > 0) {
            const ulonglong2* hq = (const ulonglong2*)&hsh[buf][0];
            unsigned long long a0 = 0ull, a1 = 0ull, a2 = 0ull, a3 = 0ull;
            #pragma unroll
            for (int j = 0; j < 16; j += 2) {
                ulonglong2 h0 = hq[ksub + 8 * j];
                ulonglong2 h1 = hq[ksub + 8 * (j + 1)];
                ffma2(a0, w2[2 * j],     h0.x);
                ffma2(a1, w2[2 * j + 1], h0.y);
                ffma2(a2, w2[2 * j + 2], h1.x);
                ffma2(a3, w2[2 * j + 3], h1.y);
            }
            float2 f0 = unpack2(a0), f1 = unpack2(a1);
            float2 f2 = unpack2(a2), f3 = unpack2(a3);
            part = ((f0.x + f0.y) + (f1.x + f1.y)) + ((f2.x + f2.y) + (f3.x + f3.y));
        }
        if (ksub == 0) part += gxv;

        // 8-way shfl reduction within each gate-row group
        part += __shfl_down_sync(0xffffffffu, part, 4, 8);
        part += __shfl_down_sync(0xffffffffu, part, 2, 8);
        part += __shfl_down_sync(0xffffffffu, part, 1, 8);

        // lanes 0,8,16,24 hold gate sums i,f,g,o -> nonlinearity in parallel
        float nl = (gate == 2) ? tanh_f(part) : sigm_f(part);
        float sf = __shfl_sync(0xffffffffu, nl, 8);
        float tg = __shfl_sync(0xffffffffu, nl, 16);
        float so = __shfl_sync(0xffffffffu, nl, 24);

        if (lane == 0) {
            c_state = sf * c_state + nl * tg;      // nl = sigm(i) at lane 0
            float h = so * tanh_f(c_state);
            unsigned hb = (__float_as_uint(h) & ~3u) | (unsigned)(s & 3);
            float he = __uint_as_float(hb);
            float* dst = ((s & 1) ? slotB : slotA) + unit;
            asm volatile("st.volatile.global.f32 [%0], %1;" :: "l"(dst), "f"(he));
            y[(size_t)tt * Y1DIM + dir * HID + unit] = he;
        }
    }
}

// ---------------- tag head: logits = y1 @ h2t_w^T + b ----------------
__global__ void h2t_kernel(const float* __restrict__ Y, const float* __restrict__ W,
                           const float* __restrict__ B, float* __restrict__ L)
{
    int id = blockIdx.x * blockDim.x + threadIdx.x;
    int t = id >> 5;
    int n = id & 31;
    if (t >= TT || n >= TAGS) return;
    const float4* yr = (const float4*)(Y + (size_t)t * Y1DIM);
    const float4* wr = (const float4*)(W + (size_t)n * Y1DIM);
    float acc = 0.f;
    #pragma unroll 8
    for (int k = 0; k < Y1DIM / 4; k++) {
        float4 a = yr[k], b = wr[k];
        acc = fmaf(a.x, b.x, acc);
        acc = fmaf(a.y, b.y, acc);
        acc = fmaf(a.z, b.z, acc);
        acc = fmaf(a.w, b.w, acc);
    }
    L[t * 32 + n] = acc + B[n];
}

// ---------------- Viterbi (single warp, backpointers in SMEM) ----------------
__global__ void viterbi_kernel(const float* __restrict__ L, const float* __restrict__ trans,
                               float* __restrict__ out, int out_size)
{
    extern __shared__ unsigned char sm[];
    unsigned char* bp = sm;                              // TT * TAGS bytes
    float* fvs = (float*)(sm + TT * TAGS);
    const int lane = threadIdx.x;

    float tr[TAGS];
    if (lane < TAGS) {
        #pragma unroll
        for (int p = 0; p < TAGS; p++) tr[p] = trans[lane * TAGS + p];
        fvs[lane] = (lane == STARTT) ? 0.f : -10000.f;
    }
    __syncwarp();

    float feat = (lane < TAGS) ? L[lane] : 0.f;
    for (int t = 0; t < TT; t++) {
        float nfeat = 0.f;
        if (t + 1 < TT && lane < TAGS) nfeat = L[(t + 1) * 32 + lane];

        float best = 0.f;
        int arg = 0;
        if (lane < TAGS) {
            float sc[TAGS];
            float v[32];
            #pragma unroll
            for (int p = 0; p < TAGS; p++) { sc[p] = fvs[p] + tr[p]; v[p] = sc[p]; }
            #pragma unroll
            for (int p = TAGS; p < 32; p++) v[p] = -3.4e38f;
            #pragma unroll
            for (int st = 16; st >= 1; st >>= 1)
                #pragma unroll
                for (int i = 0; i < 16; i++)
                    if (i < st) v[i] = fmaxf(v[i], v[i + st]);
            best = v[0];
            unsigned mask = 0;
            #pragma unroll
            for (int p = 0; p < TAGS; p++)
                mask |= (sc[p] == best) ? (1u << p) : 0u;
            arg = __ffs(mask) - 1;                       // first (lowest) argmax
        }
        __syncwarp();
        if (lane < TAGS) {
            fvs[lane] = best + feat;
            bp[t * TAGS + lane] = (unsigned char)arg;
        }
        __syncwarp();
        feat = nfeat;
    }

    float term = (lane < TAGS) ? fvs[lane] + trans[STOPT * TAGS + lane] : -3.4e38f;
    int bi = lane;
    #pragma unroll
    for (int off = 16; off > 0; off >>= 1) {
        float ov = __shfl_down_sync(0xffffffff, term, off);
        int   oi = __shfl_down_sync(0xffffffff, bi,   off);
        if (ov > term || (ov == term && oi < bi)) { term = ov; bi = oi; }
    }
    term = __shfl_sync(0xffffffff, term, 0);
    bi   = __shfl_sync(0xffffffff, bi,   0);

    if (lane == 0) {
        float* po = out;
        if (out_size > TT) { out[0] = term; po = out + 1; }
        int tag = bi;
        for (int t = TT - 1; t >= 0; t--) {
            po[t] = (float)tag;
            tag = bp[t * TAGS + tag];
        }
    }
}

// ---------------- launcher ----------------
extern "C" void kernel_launch(void* const* d_in, const int* in_sizes, int n_in,
                              void* d_out, int out_size)
{
    const float* features = (const float*)d_in[0];
    const float* conv1_w  = (const float*)d_in[1];
    const float* conv1_b  = (const float*)d_in[2];
    const float* conv3_w  = (const float*)d_in[3];
    const float* conv3_b  = (const float*)d_in[4];
    const float* conv5_w  = (const float*)d_in[5];
    const float* conv5_b  = (const float*)d_in[6];
    const float* wih0f = (const float*)d_in[7];
    const float* whh0f = (const float*)d_in[8];
    const float* bih0f = (const float*)d_in[9];
    const float* bhh0f = (const float*)d_in[10];
    const float* wih0r = (const float*)d_in[11];
    const float* whh0r = (const float*)d_in[12];
    const float* bih0r = (const float*)d_in[13];
    const float* bhh0r = (const float*)d_in[14];
    const float* wih1f = (const float*)d_in[15];
    const float* whh1f = (const float*)d_in[16];
    const float* bih1f = (const float*)d_in[17];
    const float* bhh1f = (const float*)d_in[18];
    const float* wih1r = (const float*)d_in[19];
    const float* whh1r = (const float*)d_in[20];
    const float* bih1r = (const float*)d_in[21];
    const float* bhh1r = (const float*)d_in[22];
    const float* h2t_w = (const float*)d_in[23];
    const float* h2t_b = (const float*)d_in[24];
    const float* trans = (const float*)d_in[25];

    float* out = (float*)d_out;

    float* px   = nullptr; cudaGetSymbolAddress((void**)&px,   d_x);
    float* pgxf = nullptr; cudaGetSymbolAddress((void**)&pgxf, d_gxf);
    float* pgxr = nullptr; cudaGetSymbolAddress((void**)&pgxr, d_gxr);
    float* py0  = nullptr; cudaGetSymbolAddress((void**)&py0,  d_y0);
    float* py1  = nullptr; cudaGetSymbolAddress((void**)&py1,  d_y1);
    float* plog = nullptr; cudaGetSymbolAddress((void**)&plog, d_logits);

    // 1. poison mailboxes (both layers, both slots)
    zero_mail_kernel<<<1, 256>>>();

    // 2. conv features
    conv_kernel<<<TT, 128>>>(features, conv1_w, conv1_b, conv3_w, conv3_b,
                             conv5_w, conv5_b, px);

    // 3. layer 0 input-gate GEMMs (fwd + bwd)
    dim3 ggrid(GATES / 128, TT / 128, 2);
    gemm_dual_kernel<<<ggrid, 256>>>(px,
                                     wih0f, bih0f, bhh0f, pgxf,
                                     wih0r, bih0r, bhh0r, pgxr,
                                     TT, GATES, DIN);

    // 4. layer 0 recurrence
    recur_kernel<<<2 * RC_C, 256>>>(pgxf, pgxr, whh0f, whh0r, py0, 0);

    // 5. layer 1 input-gate GEMMs
    gemm_dual_kernel<<<ggrid, 256>>>(py0,
                                     wih1f, bih1f, bhh1f, pgxf,
                                     wih1r, bih1r, bhh1r, pgxr,
                                     TT, GATES, Y1DIM);

    // 6. layer 1 recurrence
    recur_kernel<<<2 * RC_C, 256>>>(pgxf, pgxr, whh1f, whh1r, py1, 1);

    // 7. tag logits
    h2t_kernel<<<(TT * 32) / 256, 256>>>(py1, h2t_w, h2t_b, plog);

    // 8. Viterbi decode + output
    const int vit_smem = TT * TAGS + 32 * sizeof(float);
    cudaFuncSetAttribute(viterbi_kernel, cudaFuncAttributeMaxDynamicSharedMemorySize, vit_smem);
    viterbi_kernel<<<1, 32, vit_smem>>>(plog, trans, out, out_size);
}

// round 9
// speedup vs baseline: 1.2139x; 1.2139x over previous
#include <cuda_runtime.h>
#include <cuda_bf16.h>
#include <math.h>

// ---------------- problem constants ----------------
#define TT      8192
#define DIN     1728
#define HID     512
#define GATES   2048
#define Y1DIM   1024
#define TAGS    27
#define STARTT  25
#define STOPT   26

// recurrence partitioning: 64 CTAs per direction, 8 hidden units per CTA
#define RC_C    64
#define RC_U    8

// ---------------- device scratch ----------------
__device__ float d_x   [TT * DIN];
__device__ float d_gxf [TT * GATES];
__device__ float d_gxr [TT * GATES];
__device__ float d_y0  [TT * Y1DIM];
__device__ float d_y1  [TT * Y1DIM];
__device__ float d_logits[TT * 32];

// self-validating mailboxes: [layer][dir][slot][unit]
// each float carries (step & 3) in its 2 LSBs; slot = step & 1
__device__ float d_mail[2][2][2][RC_C * RC_U];

// ---------------- f32x2 helpers ----------------
__device__ __forceinline__ void ffma2(unsigned long long& d,
                                      unsigned long long a, unsigned long long b) {
    asm("fma.rn.f32x2 %0, %1, %2, %0;" : "+l"(d) : "l"(a), "l"(b));
}
__device__ __forceinline__ unsigned long long pack2(float x, float y) {
    unsigned long long r;
    asm("mov.b64 %0, {%1, %2};" : "=l"(r) : "f"(x), "f"(y));
    return r;
}
__device__ __forceinline__ float2 unpack2(unsigned long long v) {
    float2 r;
    asm("mov.b64 {%0, %1}, %2;" : "=f"(r.x), "=f"(r.y) : "l"(v));
    return r;
}

// fast gates (MUFU-based, clamp-safe)
__device__ __forceinline__ float sigm_f(float x) {
    return __fdividef(1.f, 1.f + __expf(-x));
}
__device__ __forceinline__ float tanh_f(float x) {
    float e = __expf(-2.f * fabsf(x));          // e in (0,1] -> no inf/NaN
    float r = __fdividef(1.f - e, 1.f + e);
    return copysignf(r, x);
}

// ---------------- mailbox poison ----------------
// slot0 holds even-step tags {0,2}: poison with tag 1.
// slot1 holds odd-step tags {1,3}: poison with tag 0.
__global__ void zero_mail_kernel()
{
    float* base = &d_mail[0][0][0][0];
    const int total = 2 * 2 * 2 * RC_C * RC_U;          // 4096
    for (int i = threadIdx.x; i < total; i += blockDim.x) {
        int slot = (i >> 9) & 1;
        unsigned bits = slot ? 0u : 1u;
        base[i] = __uint_as_float(bits);
    }
}

// ---------------- conv feature kernel ----------------
__global__ void conv_kernel(const float* __restrict__ F,
                            const float* __restrict__ W1, const float* __restrict__ B1,
                            const float* __restrict__ W3, const float* __restrict__ B3,
                            const float* __restrict__ W5, const float* __restrict__ B5,
                            float* __restrict__ X)
{
    int t = blockIdx.x;
    __shared__ float fsh[448];
    __shared__ float w1s[448];
    __shared__ float w3s[768];
    __shared__ float w5s[1280];
    __shared__ float b1s[16], b3s[16], b5s[16];
    int tid = threadIdx.x;   // 128 threads

    for (int i = tid; i < 448;  i += 128) fsh[i] = F[t * 448 + i];
    for (int i = tid; i < 448;  i += 128) w1s[i] = W1[i];
    for (int i = tid; i < 768;  i += 128) w3s[i] = W3[i];
    for (int i = tid; i < 1280; i += 128) w5s[i] = W5[i];
    if (tid < 16) { b1s[tid] = B1[tid]; b3s[tid] = B3[tid]; b5s[tid] = B5[tid]; }
    __syncthreads();

    for (int idx = tid; idx < DIN; idx += 128) {
        float acc;
        if (idx < 192) {
            int c = idx / 12, w = idx % 12;
            acc = b1s[c];
            #pragma unroll
            for (int kh = 0; kh < 7; kh++)
                #pragma unroll
                for (int kw = 0; kw < 4; kw++)
                    acc = fmaf(fsh[kh * 64 + w * 4 + kw], w1s[c * 28 + kh * 4 + kw], acc);
        } else if (idx < 960) {
            int j = idx - 192;
            int c = j / 48, r = j % 48, h = r / 12, w = r % 12;
            acc = b3s[c];
            #pragma unroll
            for (int kh = 0; kh < 4; kh++)
                #pragma unroll
                for (int kw = 0; kw < 12; kw++)
                    acc = fmaf(fsh[(h + kh) * 64 + w * 4 + kw], w3s[c * 48 + kh * 12 + kw], acc);
        } else {
            int j = idx - 960;
            int c = j / 48, r = j % 48, h = r / 12, w = r % 12;
            acc = b5s[c];
            #pragma unroll
            for (int kh = 0; kh < 4; kh++)
                #pragma unroll
                for (int kw = 0; kw < 20; kw++)
                    acc = fmaf(fsh[(h + kh) * 64 + w * 4 + kw], w5s[c * 80 + kh * 20 + kw], acc);
        }
        X[(size_t)t * DIN + idx] = acc;
    }
}

// ---------------- fp32 tiled GEMM (double-buffered, f32x2 compute), dual weight sets ----
__global__ __launch_bounds__(256) void gemm_dual_kernel(
    const float* __restrict__ A,
    const float* __restrict__ B0, const float* __restrict__ b0a,
    const float* __restrict__ b0b, float* __restrict__ C0,
    const float* __restrict__ B1, const float* __restrict__ b1a,
    const float* __restrict__ b1b, float* __restrict__ C1,
    int M, int N, int K)
{
    const float* B     = blockIdx.z ? B1  : B0;
    const float* bias1 = blockIdx.z ? b1a : b0a;
    const float* bias2 = blockIdx.z ? b1b : b0b;
    float*       C     = blockIdx.z ? C1  : C0;

    __shared__ __align__(16) float As[2][16][128];
    __shared__ __align__(16) float Bs[2][16][128];
    const int tid = threadIdx.x;
    const int m0 = blockIdx.y * 128;
    const int n0 = blockIdx.x * 128;
    const int tx = tid & 15;
    const int ty = tid >> 4;

    const int row0 = tid >> 2;
    const int row1 = row0 + 64;
    const int kq4  = (tid & 3) * 4;

    const float* Ap0 = A + (size_t)(m0 + row0) * K + kq4;
    const float* Ap1 = A + (size_t)(m0 + row1) * K + kq4;
    const float* Bp0 = B + (size_t)(n0 + row0) * K + kq4;
    const float* Bp1 = B + (size_t)(n0 + row1) * K + kq4;

    unsigned long long acc2[8][4];
    #pragma unroll
    for (int i = 0; i < 8; i++)
        #pragma unroll
        for (int j = 0; j < 4; j++) acc2[i][j] = 0ull;

    float4 pa0 = *(const float4*)(Ap0);
    float4 pa1 = *(const float4*)(Ap1);
    float4 pb0 = *(const float4*)(Bp0);
    float4 pb1 = *(const float4*)(Bp1);

    As[0][kq4 + 0][row0] = pa0.x; As[0][kq4 + 1][row0] = pa0.y;
    As[0][kq4 + 2][row0] = pa0.z; As[0][kq4 + 3][row0] = pa0.w;
    As[0][kq4 + 0][row1] = pa1.x; As[0][kq4 + 1][row1] = pa1.y;
    As[0][kq4 + 2][row1] = pa1.z; As[0][kq4 + 3][row1] = pa1.w;
    Bs[0][kq4 + 0][row0] = pb0.x; Bs[0][kq4 + 1][row0] = pb0.y;
    Bs[0][kq4 + 2][row0] = pb0.z; Bs[0][kq4 + 3][row0] = pb0.w;
    Bs[0][kq4 + 0][row1] = pb1.x; Bs[0][kq4 + 1][row1] = pb1.y;
    Bs[0][kq4 + 2][row1] = pb1.z; Bs[0][kq4 + 3][row1] = pb1.w;
    __syncthreads();

    int buf = 0;
    for (int k0 = 0; k0 < K; k0 += 16) {
        const bool more = (k0 + 16) < K;
        if (more) {
            pa0 = *(const float4*)(Ap0 + k0 + 16);
            pa1 = *(const float4*)(Ap1 + k0 + 16);
            pb0 = *(const float4*)(Bp0 + k0 + 16);
            pb1 = *(const float4*)(Bp1 + k0 + 16);
        }

        #pragma unroll
        for (int k = 0; k < 16; k++) {
            float4 a0 = *(const float4*)&As[buf][k][ty * 8];
            float4 a1 = *(const float4*)&As[buf][k][ty * 8 + 4];
            unsigned long long b2[4];
            {
                const ulonglong2* bp = (const ulonglong2*)&Bs[buf][k][tx * 8];
                ulonglong2 v0 = bp[0], v1 = bp[1];
                b2[0] = v0.x; b2[1] = v0.y; b2[2] = v1.x; b2[3] = v1.y;
            }
            float av[8] = {a0.x, a0.y, a0.z, a0.w, a1.x, a1.y, a1.z, a1.w};
            #pragma unroll
            for (int i = 0; i < 8; i++) {
                unsigned long long ai = pack2(av[i], av[i]);
                #pragma unroll
                for (int jp = 0; jp < 4; jp++)
                    ffma2(acc2[i][jp], ai, b2[jp]);
            }
        }

        if (more) {
            int nb = buf ^ 1;
            As[nb][kq4 + 0][row0] = pa0.x; As[nb][kq4 + 1][row0] = pa0.y;
            As[nb][kq4 + 2][row0] = pa0.z; As[nb][kq4 + 3][row0] = pa0.w;
            As[nb][kq4 + 0][row1] = pa1.x; As[nb][kq4 + 1][row1] = pa1.y;
            As[nb][kq4 + 2][row1] = pa1.z; As[nb][kq4 + 3][row1] = pa1.w;
            Bs[nb][kq4 + 0][row0] = pb0.x; Bs[nb][kq4 + 1][row0] = pb0.y;
            Bs[nb][kq4 + 2][row0] = pb0.z; Bs[nb][kq4 + 3][row0] = pb0.w;
            Bs[nb][kq4 + 0][row1] = pb1.x; Bs[nb][kq4 + 1][row1] = pb1.y;
            Bs[nb][kq4 + 2][row1] = pb1.z; Bs[nb][kq4 + 3][row1] = pb1.w;
            __syncthreads();
            buf = nb;
        }
    }

    #pragma unroll
    for (int i = 0; i < 8; i++) {
        int m = m0 + ty * 8 + i;
        float* Crow = C + (size_t)m * N + n0 + tx * 8;
        #pragma unroll
        for (int jp = 0; jp < 4; jp++) {
            float2 v = unpack2(acc2[i][jp]);
            int n = n0 + tx * 8 + 2 * jp;
            Crow[2 * jp + 0] = v.x + bias1[n + 0] + bias2[n + 0];
            Crow[2 * jp + 1] = v.y + bias1[n + 1] + bias2[n + 1];
        }
    }
}

// ---------------- persistent bidirectional LSTM recurrence ----------------
// grid = 128 CTAs: [0,64) forward, [64,128) backward; 256 threads each.
// Warp ks computes 32 gate rows x 64-k partial (h broadcast via LDS), red in smem.
// Named-barrier split: after matvec, warps 1-7 arrive; warps 1-4 immediately poll
// NEXT step's h into the other hsh buffer while warp 0 runs the gate tail and
// publishes. Self-tagged double-buffered L2 mailboxes, single hop.
__global__ __launch_bounds__(256, 1) void recur_kernel(
    const float* __restrict__ gx_f, const float* __restrict__ gx_r,
    const float* __restrict__ whh_f, const float* __restrict__ whh_r,
    float* __restrict__ y, int layer)
{
    const int dir = blockIdx.x >> 6;
    const int cta = blockIdx.x & 63;
    const float* __restrict__ gx  = dir ? gx_r  : gx_f;
    const float* __restrict__ whh = dir ? whh_r : whh_f;
    float* slotA = &d_mail[layer][dir][0][0];
    float* slotB = &d_mail[layer][dir][1][0];

    const int u0   = cta * RC_U;
    const int tid  = threadIdx.x;
    const int warp = tid >> 5, lane = tid & 31;

    // matvec mapping: lane = gate row 0..31 of this CTA, warp = 64-wide k-slice
    const int ks    = warp;
    const int gate  = lane >> 3, uu = lane & 7;
    const int grow  = gate * 512 + u0 + uu;    // global gate row in Whh / gx
    const int kbase = ks * 64;

    __shared__ __align__(16) float hsh[2][512];   // double-buffered h
    __shared__ float red[8][32];

    // one-time: 64 weights/thread (own gate row, own k-slice) as 32 f32x2
    unsigned long long w2[32];
    {
        const ulonglong2* wp = (const ulonglong2*)(whh + (size_t)grow * 512 + kbase);
        #pragma unroll
        for (int j = 0; j < 16; j++) {
            ulonglong2 v = wp[j];
            w2[2 * j] = v.x; w2[2 * j + 1] = v.y;
        }
    }

    float c_state = 0.f;       // lives in warp 0 lanes 0..7
    float gxv_next = 0.f;      // warp 0: gx for the upcoming step
    if (warp == 0) {
        int t0 = dir ? (TT - 1) : 0;
        gxv_next = gx[(size_t)t0 * GATES + grow];
    }

    for (int s = 0; s < TT; s++) {
        const int tt  = dir ? (TT - 1 - s) : s;
        const int buf = s & 1;

        float gxv = 0.f;
        if (warp == 0) {
            gxv = gxv_next;                              // loaded one step ago
            if (s + 1 < TT) {
                int tn = dir ? (tt - 1) : (tt + 1);
                gxv_next = gx[(size_t)tn * GATES + grow];  // prefetch s+1
            }
        }

        __syncthreads();   // barrier A: hsh[buf] complete (filled last iteration)

        if (s > 0) {
            // partial matvec: 32 rows x 64 k per warp; h broadcast from shared
            const ulonglong2* hq = (const ulonglong2*)&hsh[buf][kbase];
            unsigned long long a0 = 0ull, a1 = 0ull, a2 = 0ull, a3 = 0ull;
            #pragma unroll
            for (int j = 0; j < 16; j += 2) {
                ulonglong2 h0 = hq[j];
                ulonglong2 h1 = hq[j + 1];
                ffma2(a0, w2[2 * j],     h0.x);
                ffma2(a1, w2[2 * j + 1], h0.y);
                ffma2(a2, w2[2 * j + 2], h1.x);
                ffma2(a3, w2[2 * j + 3], h1.y);
            }
            float2 f0 = unpack2(a0), f1 = unpack2(a1);
            float2 f2 = unpack2(a2), f3 = unpack2(a3);
            red[ks][lane] = ((f0.x + f0.y) + (f1.x + f1.y))
                          + ((f2.x + f2.y) + (f3.x + f3.y));
        }

        if (warp == 0) {
            // wait for all k-partials (release by arrivers, acquire here)
            asm volatile("bar.sync 1, 256;" ::: "memory");

            float sum = gxv;
            if (s > 0) {
                float s0 = red[0][lane] + red[1][lane];
                float s1 = red[2][lane] + red[3][lane];
                float s2 = red[4][lane] + red[5][lane];
                float s3 = red[6][lane] + red[7][lane];
                sum += (s0 + s1) + (s2 + s3);
            }
            // per-gate nonlinearity across lanes: lane = gate*8 + unit
            float nl = (gate == 2) ? tanh_f(sum) : sigm_f(sum);
            float sf = __shfl_sync(0xffffffffu, nl, lane + 8);
            float tg = __shfl_sync(0xffffffffu, nl, lane + 16);
            float so = __shfl_sync(0xffffffffu, nl, lane + 24);
            if (lane < 8) {
                c_state = sf * c_state + nl * tg;        // nl = sigm(i) on lanes 0..7
                float h = so * tanh_f(c_state);
                unsigned hb = (__float_as_uint(h) & ~3u) | (unsigned)(s & 3);
                float he = __uint_as_float(hb);
                float* dst = ((s & 1) ? slotB : slotA) + u0 + lane;
                asm volatile("st.volatile.global.f32 [%0], %1;" :: "l"(dst), "f"(he));
                y[(size_t)tt * Y1DIM + dir * HID + u0 + lane] = he;
            }
        } else {
            asm volatile("bar.arrive 1, 256;" ::: "memory");
            // warps 1-4 poll NEXT step's h (published with tag s&3 in slot s&1)
            // into the other hsh buffer, overlapping warp 0's tail + publish.
            if (warp <= 4 && s + 1 < TT) {
                const int g = tid - 32;                  // granule 0..127
                const float* src = ((s & 1) ? slotB : slotA) + (g << 2);
                const unsigned want = (unsigned)(s & 3);
                float4 v;
                unsigned bad;
                do {
                    asm volatile("ld.volatile.global.v4.f32 {%0,%1,%2,%3}, [%4];"
                                 : "=f"(v.x), "=f"(v.y), "=f"(v.z), "=f"(v.w)
                                 : "l"(src));
                    bad  = (__float_as_uint(v.x) & 3u) ^ want;
                    bad |= (__float_as_uint(v.y) & 3u) ^ want;
                    bad |= (__float_as_uint(v.z) & 3u) ^ want;
                    bad |= (__float_as_uint(v.w) & 3u) ^ want;
                } while (bad);
                *(float4*)&hsh[buf ^ 1][g << 2] = v;
            }
        }
    }
}

// ---------------- tag head: logits = y1 @ h2t_w^T + b ----------------
__global__ void h2t_kernel(const float* __restrict__ Y, const float* __restrict__ W,
                           const float* __restrict__ B, float* __restrict__ L)
{
    int id = blockIdx.x * blockDim.x + threadIdx.x;
    int t = id >> 5;
    int n = id & 31;
    if (t >= TT || n >= TAGS) return;
    const float4* yr = (const float4*)(Y + (size_t)t * Y1DIM);
    const float4* wr = (const float4*)(W + (size_t)n * Y1DIM);
    float acc = 0.f;
    #pragma unroll 8
    for (int k = 0; k < Y1DIM / 4; k++) {
        float4 a = yr[k], b = wr[k];
        acc = fmaf(a.x, b.x, acc);
        acc = fmaf(a.y, b.y, acc);
        acc = fmaf(a.z, b.z, acc);
        acc = fmaf(a.w, b.w, acc);
    }
    L[t * 32 + n] = acc + B[n];
}

// ---------------- Viterbi (single warp, backpointers in SMEM) ----------------
__global__ void viterbi_kernel(const float* __restrict__ L, const float* __restrict__ trans,
                               float* __restrict__ out, int out_size)
{
    extern __shared__ unsigned char sm[];
    unsigned char* bp = sm;                              // TT * TAGS bytes
    float* fvs = (float*)(sm + TT * TAGS);
    const int lane = threadIdx.x;

    float tr[TAGS];
    if (lane < TAGS) {
        #pragma unroll
        for (int p = 0; p < TAGS; p++) tr[p] = trans[lane * TAGS + p];
        fvs[lane] = (lane == STARTT) ? 0.f : -10000.f;
    }
    __syncwarp();

    float feat = (lane < TAGS) ? L[lane] : 0.f;
    for (int t = 0; t < TT; t++) {
        float nfeat = 0.f;
        if (t + 1 < TT && lane < TAGS) nfeat = L[(t + 1) * 32 + lane];

        float best = 0.f;
        int arg = 0;
        if (lane < TAGS) {
            float sc[TAGS];
            float v[32];
            #pragma unroll
            for (int p = 0; p < TAGS; p++) { sc[p] = fvs[p] + tr[p]; v[p] = sc[p]; }
            #pragma unroll
            for (int p = TAGS; p < 32; p++) v[p] = -3.4e38f;
            #pragma unroll
            for (int st = 16; st >= 1; st >>= 1)
                #pragma unroll
                for (int i = 0; i < 16; i++)
                    if (i < st) v[i] = fmaxf(v[i], v[i + st]);
            best = v[0];
            unsigned mask = 0;
            #pragma unroll
            for (int p = 0; p < TAGS; p++)
                mask |= (sc[p] == best) ? (1u << p) : 0u;
            arg = __ffs(mask) - 1;                       // first (lowest) argmax
        }
        __syncwarp();
        if (lane < TAGS) {
            fvs[lane] = best + feat;
            bp[t * TAGS + lane] = (unsigned char)arg;
        }
        __syncwarp();
        feat = nfeat;
    }

    float term = (lane < TAGS) ? fvs[lane] + trans[STOPT * TAGS + lane] : -3.4e38f;
    int bi = lane;
    #pragma unroll
    for (int off = 16; off > 0; off >>= 1) {
        float ov = __shfl_down_sync(0xffffffff, term, off);
        int   oi = __shfl_down_sync(0xffffffff, bi,   off);
        if (ov > term || (ov == term && oi < bi)) { term = ov; bi = oi; }
    }
    term = __shfl_sync(0xffffffff, term, 0);
    bi   = __shfl_sync(0xffffffff, bi,   0);

    if (lane == 0) {
        float* po = out;
        if (out_size > TT) { out[0] = term; po = out + 1; }
        int tag = bi;
        for (int t = TT - 1; t >= 0; t--) {
            po[t] = (float)tag;
            tag = bp[t * TAGS + tag];
        }
    }
}

// ---------------- launcher ----------------
extern "C" void kernel_launch(void* const* d_in, const int* in_sizes, int n_in,
                              void* d_out, int out_size)
{
    const float* features = (const float*)d_in[0];
    const float* conv1_w  = (const float*)d_in[1];
    const float* conv1_b  = (const float*)d_in[2];
    const float* conv3_w  = (const float*)d_in[3];
    const float* conv3_b  = (const float*)d_in[4];
    const float* conv5_w  = (const float*)d_in[5];
    const float* conv5_b  = (const float*)d_in[6];
    const float* wih0f = (const float*)d_in[7];
    const float* whh0f = (const float*)d_in[8];
    const float* bih0f = (const float*)d_in[9];
    const float* bhh0f = (const float*)d_in[10];
    const float* wih0r = (const float*)d_in[11];
    const float* whh0r = (const float*)d_in[12];
    const float* bih0r = (const float*)d_in[13];
    const float* bhh0r = (const float*)d_in[14];
    const float* wih1f = (const float*)d_in[15];
    const float* whh1f = (const float*)d_in[16];
    const float* bih1f = (const float*)d_in[17];
    const float* bhh1f = (const float*)d_in[18];
    const float* wih1r = (const float*)d_in[19];
    const float* whh1r = (const float*)d_in[20];
    const float* bih1r = (const float*)d_in[21];
    const float* bhh1r = (const float*)d_in[22];
    const float* h2t_w = (const float*)d_in[23];
    const float* h2t_b = (const float*)d_in[24];
    const float* trans = (const float*)d_in[25];

    float* out = (float*)d_out;

    float* px   = nullptr; cudaGetSymbolAddress((void**)&px,   d_x);
    float* pgxf = nullptr; cudaGetSymbolAddress((void**)&pgxf, d_gxf);
    float* pgxr = nullptr; cudaGetSymbolAddress((void**)&pgxr, d_gxr);
    float* py0  = nullptr; cudaGetSymbolAddress((void**)&py0,  d_y0);
    float* py1  = nullptr; cudaGetSymbolAddress((void**)&py1,  d_y1);
    float* plog = nullptr; cudaGetSymbolAddress((void**)&plog, d_logits);

    // 1. poison mailboxes (both layers, both slots)
    zero_mail_kernel<<<1, 256>>>();

    // 2. conv features
    conv_kernel<<<TT, 128>>>(features, conv1_w, conv1_b, conv3_w, conv3_b,
                             conv5_w, conv5_b, px);

    // 3. layer 0 input-gate GEMMs (fwd + bwd)
    dim3 ggrid(GATES / 128, TT / 128, 2);
    gemm_dual_kernel<<<ggrid, 256>>>(px,
                                     wih0f, bih0f, bhh0f, pgxf,
                                     wih0r, bih0r, bhh0r, pgxr,
                                     TT, GATES, DIN);

    // 4. layer 0 recurrence
    recur_kernel<<<2 * RC_C, 256>>>(pgxf, pgxr, whh0f, whh0r, py0, 0);

    // 5. layer 1 input-gate GEMMs
    gemm_dual_kernel<<<ggrid, 256>>>(py0,
                                     wih1f, bih1f, bhh1f, pgxf,
                                     wih1r, bih1r, bhh1r, pgxr,
                                     TT, GATES, Y1DIM);

    // 6. layer 1 recurrence
    recur_kernel<<<2 * RC_C, 256>>>(pgxf, pgxr, whh1f, whh1r, py1, 1);

    // 7. tag logits
    h2t_kernel<<<(TT * 32) / 256, 256>>>(py1, h2t_w, h2t_b, plog);

    // 8. Viterbi decode + output
    const int vit_smem = TT * TAGS + 32 * sizeof(float);
    cudaFuncSetAttribute(viterbi_kernel, cudaFuncAttributeMaxDynamicSharedMemorySize, vit_smem);
    viterbi_kernel<<<1, 32, vit_smem>>>(plog, trans, out, out_size);
}